// round 1
// baseline (speedup 1.0000x reference)
#include <cuda_runtime.h>
#include <cstdint>
#include <math.h>

#define Bn 256
#define Sn 512
#define Hn 64
#define En 330
#define Tn 16
#define Gn 256   // 4H
#define START_IX 14
#define STOP_IX 15

// table row bases inside the concatenated projected table
// word:20000 w=100 off=0 | flag:60 w=50 off=100 | bound:8 w=50 off=150
// radical:300 w=50 off=200 | pinyin:500 w=80 off=250
#define NROWS_TOTAL 20868

// ---- scratch (static device memory; no allocations allowed) ----
__device__ float g_WT[En * 512];                       // Wih transposed+concat [E][512]
__device__ float g_bias[512];                          // bih+bhh per direction, concat
__device__ float g_proj[(size_t)NROWS_TOTAL * 512];    // projected tables  ~42.7MB
__device__ float g_xp[2][(size_t)Sn * Bn * Gn];        // x-projections     2x134MB
__device__ float g_h[2][(size_t)Sn * Bn * Hn];         // lstm hidden       2x33.5MB
__device__ float g_feats[(size_t)Sn * Bn * Tn];        // emissions         8.4MB

__device__ __forceinline__ float sigf(float x) {
    return 1.0f / (1.0f + __expf(-x));
}

// ---- K0: transpose Wih_f/Wih_b into [E][512] and fold biases ----
__global__ void prep_kernel(const float* __restrict__ Wf, const float* __restrict__ Wb,
                            const float* __restrict__ bihf, const float* __restrict__ bhhf,
                            const float* __restrict__ bihb, const float* __restrict__ bhhb) {
    int idx = blockIdx.x * blockDim.x + threadIdx.x;
    if (idx < En * 512) {
        int c = idx / 512, j = idx % 512;
        g_WT[idx] = (j < 256) ? Wf[j * En + c] : Wb[(j - 256) * En + c];
    }
    if (idx < 512) {
        g_bias[idx] = (idx < 256) ? (bihf[idx] + bhhf[idx]) : (bihb[idx - 256] + bhhb[idx - 256]);
    }
}

// ---- K1: project one embedding table into g_proj (both directions at once) ----
__global__ void proj_kernel(const float* __restrict__ emb, int nrows, int width,
                            int segoff, int base) {
    const int r0 = blockIdx.x * 8;
    const int j = threadIdx.x;             // 512 threads = output column
    __shared__ float es[8][100];
    for (int i = threadIdx.x; i < 8 * width; i += 512) {
        int rr = i / width, kk = i % width;
        if (r0 + rr < nrows) es[rr][kk] = emb[(size_t)(r0 + rr) * width + kk];
    }
    __syncthreads();
    float acc[8] = {0.f, 0.f, 0.f, 0.f, 0.f, 0.f, 0.f, 0.f};
    for (int k = 0; k < width; k++) {
        float wv = g_WT[(size_t)(segoff + k) * 512 + j];
#pragma unroll
        for (int r = 0; r < 8; r++) acc[r] += es[r][k] * wv;
    }
#pragma unroll
    for (int r = 0; r < 8; r++)
        if (r0 + r < nrows) g_proj[(size_t)(base + r0 + r) * 512 + j] = acc[r];
}

// ---- K2: gather-sum 5 projected rows + bias -> xproj for both dirs ----
__global__ void gather_kernel(const int* __restrict__ wi, const int* __restrict__ fi,
                              const int* __restrict__ bi, const int* __restrict__ ri,
                              const int* __restrict__ pi) {
    const int sb = blockIdx.x;             // sb = s*B + b
    const int s = sb >> 8, b = sb & 255;
    const int j = threadIdx.x;             // 512
    const int iw = wi[b * Sn + s];
    const int ifl = fi[b * Sn + s];
    const int ib = bi[b * Sn + s];
    const int ir = ri[b * Sn + s];
    const int ip = pi[b * Sn + s];
    float v = g_bias[j]
            + g_proj[(size_t)iw * 512 + j]
            + g_proj[(size_t)(20000 + ifl) * 512 + j]
            + g_proj[(size_t)(20060 + ib) * 512 + j]
            + g_proj[(size_t)(20068 + ir) * 512 + j]
            + g_proj[(size_t)(20368 + ip) * 512 + j];
    if (j < 256) g_xp[0][(size_t)sb * Gn + j] = v;
    else         g_xp[1][(size_t)sb * Gn + (j - 256)] = v;
}

// ---- K3: the recurrence. gridDim=(64,2), 256 threads. Bc=4 batch/CTA. ----
__global__ __launch_bounds__(256, 1)
void lstm_kernel(const float* __restrict__ Whh_f, const float* __restrict__ Whh_b,
                 const float* __restrict__ h0, const float* __restrict__ c0) {
    const int dir = blockIdx.y;
    const int b0 = blockIdx.x * 4;
    const float* __restrict__ Whh = dir ? Whh_b : Whh_f;
    const float* __restrict__ xp = g_xp[dir];
    float* __restrict__ hout = g_h[dir];
    const int j = threadIdx.x;             // gate-output index 0..255

    float w[64];
#pragma unroll
    for (int k = 0; k < 64; k++) w[k] = Whh[j * 64 + k];

    __shared__ __align__(16) float h_sh[4][64];
    __shared__ float z_sh[4][256];

    const int cb = j >> 6, ck = j & 63;    // this thread's cell (batch, hidden)
    float c = c0[dir * Bn * Hn + (b0 + cb) * Hn + ck];
    h_sh[cb][ck] = h0[dir * Bn * Hn + (b0 + cb) * Hn + ck];

    int t = dir ? (Sn - 1) : 0;
    const float* xr = xp + ((size_t)t * Bn + b0) * Gn + j;
    float xc0 = xr[0], xc1 = xr[Gn], xc2 = xr[2 * Gn], xc3 = xr[3 * Gn];
    __syncthreads();

    for (int step = 0; step < Sn; step++) {
        // prefetch next step's x-projection (hide DRAM latency under compute)
        float xn0 = 0.f, xn1 = 0.f, xn2 = 0.f, xn3 = 0.f;
        if (step + 1 < Sn) {
            int tn = dir ? (t - 1) : (t + 1);
            const float* xn = xp + ((size_t)tn * Bn + b0) * Gn + j;
            xn0 = xn[0]; xn1 = xn[Gn]; xn2 = xn[2 * Gn]; xn3 = xn[3 * Gn];
        }
        float a0 = xc0, a1 = xc1, a2 = xc2, a3 = xc3;
#pragma unroll
        for (int k = 0; k < 64; k += 4) {
            float4 hv0 = *(const float4*)&h_sh[0][k];
            float4 hv1 = *(const float4*)&h_sh[1][k];
            float4 hv2 = *(const float4*)&h_sh[2][k];
            float4 hv3 = *(const float4*)&h_sh[3][k];
            a0 += hv0.x * w[k] + hv0.y * w[k + 1] + hv0.z * w[k + 2] + hv0.w * w[k + 3];
            a1 += hv1.x * w[k] + hv1.y * w[k + 1] + hv1.z * w[k + 2] + hv1.w * w[k + 3];
            a2 += hv2.x * w[k] + hv2.y * w[k + 1] + hv2.z * w[k + 2] + hv2.w * w[k + 3];
            a3 += hv3.x * w[k] + hv3.y * w[k + 1] + hv3.z * w[k + 2] + hv3.w * w[k + 3];
        }
        z_sh[0][j] = a0; z_sh[1][j] = a1; z_sh[2][j] = a2; z_sh[3][j] = a3;
        __syncthreads();

        float zi = z_sh[cb][ck];
        float zf = z_sh[cb][64 + ck];
        float zg = z_sh[cb][128 + ck];
        float zo = z_sh[cb][192 + ck];
        c = sigf(zf) * c + sigf(zi) * tanhf(zg);
        float hh = sigf(zo) * tanhf(c);
        h_sh[cb][ck] = hh;
        hout[((size_t)t * Bn + b0 + cb) * Hn + ck] = hh;
        __syncthreads();

        xc0 = xn0; xc1 = xn1; xc2 = xn2; xc3 = xn3;
        t = dir ? (t - 1) : (t + 1);
    }
}

// ---- K4: emissions feats = [hf|hb] @ Wout^T + bout ----
__global__ void feats_kernel(const float* __restrict__ Wout, const float* __restrict__ bout) {
    const int p = blockIdx.x * 16 + (threadIdx.x >> 4);  // sb index
    const int jj = threadIdx.x & 15;
    const float* hf = g_h[0] + (size_t)p * Hn;
    const float* hb = g_h[1] + (size_t)p * Hn;
    const float* w0 = Wout + jj * 128;
    float acc = bout[jj];
#pragma unroll 8
    for (int k = 0; k < 64; k++) acc += hf[k] * w0[k] + hb[k] * w0[64 + k];
    g_feats[(size_t)p * Tn + jj] = acc;
}

// ---- K5: CRF forward algorithm + real path score -> loss ----
__global__ void crf_kernel(const float* __restrict__ transitions,
                           const int* __restrict__ tags, float* __restrict__ out) {
    const int b = blockIdx.x * 16 + (threadIdx.x >> 4);
    const int n = threadIdx.x & 15;        // "next" tag this lane owns
    const unsigned FULL = 0xFFFFFFFFu;

    float tr[16];
#pragma unroll
    for (int k = 0; k < 16; k++) tr[k] = transitions[n * 16 + k];
    float tmax = tr[0];
#pragma unroll
    for (int k = 1; k < 16; k++) tmax = fmaxf(tmax, tr[k]);
    float expT[16];
#pragma unroll
    for (int k = 0; k < 16; k++) expT[k] = __expf(tr[k] - tmax);

    float alpha = (n == START_IX) ? 0.f : -10000.f;
    for (int s = 0; s < Sn; s++) {
        float feat = g_feats[((size_t)s * Bn + b) * Tn + n];
        float m = alpha;
        for (int o = 8; o; o >>= 1) m = fmaxf(m, __shfl_xor_sync(FULL, m, o, 16));
        float e = __expf(alpha - m);
        float acc = 0.f;
#pragma unroll
        for (int k = 0; k < 16; k++) acc += __shfl_sync(FULL, e, k, 16) * expT[k];
        alpha = feat + m + tmax + __logf(acc);
    }
    // all-path score: LSE(alpha + trans[STOP,:])
    float v = alpha + transitions[STOP_IX * 16 + n];
    float m2 = v;
    for (int o = 8; o; o >>= 1) m2 = fmaxf(m2, __shfl_xor_sync(FULL, m2, o, 16));
    float se = __expf(v - m2);
    for (int o = 8; o; o >>= 1) se += __shfl_xor_sync(FULL, se, o, 16);
    float all_sc = m2 + __logf(se);

    // real path score: lanes stride over s
    float rp = 0.f;
    for (int s = n; s < Sn; s += 16) {
        int tg = tags[b * Sn + s];
        int pv = (s == 0) ? START_IX : tags[b * Sn + s - 1];
        rp += g_feats[((size_t)s * Bn + b) * Tn + tg] + transitions[tg * 16 + pv];
    }
    for (int o = 8; o; o >>= 1) rp += __shfl_xor_sync(FULL, rp, o, 16);

    if (n == 0) {
        float real = rp + transitions[STOP_IX * 16 + tags[b * Sn + Sn - 1]];
        out[b] = all_sc - real;
    }
}

extern "C" void kernel_launch(void* const* d_in, const int* in_sizes, int n_in,
                              void* d_out, int out_size) {
    const float* word_emb    = (const float*)d_in[0];
    const float* flag_emb    = (const float*)d_in[1];
    const float* bound_emb   = (const float*)d_in[2];
    const float* radical_emb = (const float*)d_in[3];
    const float* pinyin_emb  = (const float*)d_in[4];
    const float* Wih_f = (const float*)d_in[5];
    const float* Whh_f = (const float*)d_in[6];
    const float* bih_f = (const float*)d_in[7];
    const float* bhh_f = (const float*)d_in[8];
    const float* Wih_b = (const float*)d_in[9];
    const float* Whh_b = (const float*)d_in[10];
    const float* bih_b = (const float*)d_in[11];
    const float* bhh_b = (const float*)d_in[12];
    const float* Wout  = (const float*)d_in[13];
    const float* bout  = (const float*)d_in[14];
    const float* transitions = (const float*)d_in[15];
    const float* h0 = (const float*)d_in[16];
    const float* c0 = (const float*)d_in[17];
    const int* word_ids    = (const int*)d_in[18];
    const int* flag_ids    = (const int*)d_in[19];
    const int* bound_ids   = (const int*)d_in[20];
    const int* radical_ids = (const int*)d_in[21];
    const int* pinyin_ids  = (const int*)d_in[22];
    const int* tags        = (const int*)d_in[23];

    prep_kernel<<<(En * 512 + 255) / 256, 256>>>(Wih_f, Wih_b, bih_f, bhh_f, bih_b, bhh_b);

    proj_kernel<<<(20000 + 7) / 8, 512>>>(word_emb,    20000, 100,   0,     0);
    proj_kernel<<<(60    + 7) / 8, 512>>>(flag_emb,       60,  50, 100, 20000);
    proj_kernel<<<1,               512>>>(bound_emb,       8,  50, 150, 20060);
    proj_kernel<<<(300   + 7) / 8, 512>>>(radical_emb,   300,  50, 200, 20068);
    proj_kernel<<<(500   + 7) / 8, 512>>>(pinyin_emb,    500,  80, 250, 20368);

    gather_kernel<<<Sn * Bn, 512>>>(word_ids, flag_ids, bound_ids, radical_ids, pinyin_ids);

    dim3 lgrid(64, 2);
    lstm_kernel<<<lgrid, 256>>>(Whh_f, Whh_b, h0, c0);

    feats_kernel<<<Sn * Bn / 16, 256>>>(Wout, bout);

    crf_kernel<<<Bn / 16, 256>>>(transitions, tags, (float*)d_out);
}